// round 4
// baseline (speedup 1.0000x reference)
#include <cuda_runtime.h>
#include <cuda_bf16.h>
#include <cstdint>

#define BB 16
#define CC 256
#define TT 1024

// Precomputed table (device global: no allocation allowed)
__device__ float g_M[256][9][256];    // [j][t][c]

// ---------------------------------------------------------------------------
// Fused kernel:
//   blocks [0,512)      : LIF (8 rows each, effw computed in-warp)
//   blocks [512,1024)   : M[j][t][c-half] prep (j=(bid-512)>>1, half=bid&1)
//   blocks [1024,3072)  : zero-fill of recon (independent of everything)
// ---------------------------------------------------------------------------
#define LIF_BLOCKS 512
#define PREP_BLOCKS 512
#define ZF_BLOCKS 2048
__global__ void __launch_bounds__(256)
fused_kernel(const float* __restrict__ x,
             const float* __restrict__ w3, const float* __restrict__ b3,
             const float* __restrict__ w5, const float* __restrict__ b5,
             const float* __restrict__ w9, const float* __restrict__ b9,
             const float* __restrict__ rw, const float* __restrict__ rb,
             const float* __restrict__ ls,
             const float* __restrict__ og, const float* __restrict__ fw,
             float* __restrict__ out_x, float* __restrict__ out_lat,
             float* __restrict__ out_act, float* __restrict__ recon) {
    __shared__ float smem[8 * 33 * 32];                 // 33792 B, reused by roles

    if (blockIdx.x >= LIF_BLOCKS + PREP_BLOCKS) {
        // =================== zero-fill role ===================
        // recon has 4,194,304 floats = 2048 blocks * 2048 floats
        const size_t base = (size_t)(blockIdx.x - (LIF_BLOCKS + PREP_BLOCKS)) * 2048;
        float4 z = make_float4(0.f, 0.f, 0.f, 0.f);
        float4* p = (float4*)(recon + base);
        p[threadIdx.x] = z;
        p[threadIdx.x + 256] = z;
        return;
    }

    if (blockIdx.x < LIF_BLOCKS) {
        // =================== LIF role ===================
        const int warp = threadIdx.x >> 5, lane = threadIdx.x & 31;
        const int row = blockIdx.x * 8 + warp;          // b*256+c
        const int c = row & 255;
        const float* xr = x + (size_t)row * TT;
        float* xo = out_x + (size_t)row * TT;
        float* sp = smem + warp * (33 * 32);

        // stage x: coalesced LDG.128, fused passthrough STG.128, conflict-free STS
        #pragma unroll
        for (int i = 0; i < 8; i++) {
            const int p = i * 128 + lane * 4;
            float4 v = *(const float4*)(xr + p);
            *(float4*)(xo + p) = v;
            const int base = 33 * (p >> 5) + (p & 31);
            sp[base + 0] = v.x; sp[base + 1] = v.y; sp[base + 2] = v.z; sp[base + 3] = v.w;
        }

        // ---- per-warp effective 9-tap kernel: lane d in [0,18) handles one dendrite ----
        float ew[9];
        #pragma unroll
        for (int i = 0; i < 9; i++) ew[i] = 0.f;
        float eb = 0.f;
        {
            const int d = lane;
            if (d < 6) {
                float r = rw[c * 18 + d];
                eb = r * b3[c * 6 + d];
                #pragma unroll
                for (int i = 0; i < 3; i++) ew[i + 3] = r * w3[(c * 6 + d) * 3 + i];
            } else if (d < 12) {
                int dd = d - 6;
                float r = rw[c * 18 + d];
                eb = r * b5[c * 6 + dd];
                #pragma unroll
                for (int i = 0; i < 5; i++) ew[i + 2] = r * w5[(c * 6 + dd) * 5 + i];
            } else if (d < 18) {
                int dd = d - 12;
                float r = rw[c * 18 + d];
                eb = r * b9[c * 6 + dd];
                #pragma unroll
                for (int i = 0; i < 9; i++) ew[i] = r * w9[(c * 6 + dd) * 9 + i];
            } else if (d == 31) {
                eb = rb[c];
            }
        }
        // butterfly reduce -> every lane gets full ew/eb
        #pragma unroll
        for (int off = 16; off; off >>= 1) {
            #pragma unroll
            for (int i = 0; i < 9; i++) ew[i] += __shfl_xor_sync(0xffffffffu, ew[i], off);
            eb += __shfl_xor_sync(0xffffffffu, eb, off);
        }
        __syncwarp();

        const float AL  = (float)0.81873075307798185567;   // exp(-1/5)
        const float OM  = (float)0.18126924692201814433;   // 1 - alpha
        const float A32 = (float)0.00166155727317393354;   // alpha^32

        const int sb = 33 * lane;
        float dloc[32];

        {   // outputs 0..7, t-offsets -4..11
            float w[16];
            #pragma unroll
            for (int q = 0; q < 4; q++)  w[q] = (lane > 0) ? sp[sb - 5 + q] : 0.f;
            #pragma unroll
            for (int q = 4; q < 16; q++) w[q] = sp[sb + q - 4];
            #pragma unroll
            for (int k = 0; k < 8; k++) {
                float d = eb;
                #pragma unroll
                for (int i = 0; i < 9; i++) d = fmaf(ew[i], w[k + i], d);
                dloc[k] = d;
            }
        }
        {   // outputs 8..15
            float w[16];
            #pragma unroll
            for (int q = 0; q < 16; q++) w[q] = sp[sb + 4 + q];
            #pragma unroll
            for (int k = 0; k < 8; k++) {
                float d = eb;
                #pragma unroll
                for (int i = 0; i < 9; i++) d = fmaf(ew[i], w[k + i], d);
                dloc[8 + k] = d;
            }
        }
        {   // outputs 16..23
            float w[16];
            #pragma unroll
            for (int q = 0; q < 16; q++) w[q] = sp[sb + 12 + q];
            #pragma unroll
            for (int k = 0; k < 8; k++) {
                float d = eb;
                #pragma unroll
                for (int i = 0; i < 9; i++) d = fmaf(ew[i], w[k + i], d);
                dloc[16 + k] = d;
            }
        }
        {   // outputs 24..31 (cross into lane+1 at offset 32)
            float w[16];
            #pragma unroll
            for (int q = 0; q < 12; q++)  w[q] = sp[sb + 20 + q];
            #pragma unroll
            for (int q = 12; q < 16; q++) w[q] = (lane < 31) ? sp[sb + 21 + q] : 0.f;
            #pragma unroll
            for (int k = 0; k < 8; k++) {
                float d = eb;
                #pragma unroll
                for (int i = 0; i < 9; i++) d = fmaf(ew[i], w[k + i], d);
                dloc[24 + k] = d;
            }
        }

        // pass 1: local segment value from V=0
        float U = 0.f, A = A32;
        #pragma unroll
        for (int ss = 0; ss < 32; ss++) U = fmaf(AL, U, OM * dloc[ss]);

        // Kogge-Stone scan over (A,U): (A1,U1)∘(A2,U2) = (A1*A2, A2*U1+U2)
        #pragma unroll
        for (int off = 1; off < 32; off <<= 1) {
            float Au = __shfl_up_sync(0xffffffffu, A, off);
            float Uu = __shfl_up_sync(0xffffffffu, U, off);
            if (lane >= off) { U = fmaf(A, Uu, U); A *= Au; }
        }
        float Vin = __shfl_up_sync(0xffffffffu, U, 1);
        if (lane == 0) Vin = 0.f;

        // pass 2: exact-order replay, first crossing
        float V = Vin;
        int lat = TT;
        const int t0 = lane * 32;
        #pragma unroll
        for (int ss = 0; ss < 32; ss++) {
            V = fmaf(AL, V, OM * dloc[ss]);
            if (lat == TT && V >= 0.01f) lat = t0 + ss;
        }
        #pragma unroll
        for (int off = 16; off; off >>= 1) lat = min(lat, __shfl_xor_sync(0xffffffffu, lat, off));

        if (lane == 0) {
            float latf = (float)lat;
            float sc = fmaxf(ls[0], 0.001f);
            out_lat[row] = latf;
            out_act[row] = expf(-latf / sc);
        }
    } else {
        // =================== M-prep role ===================
        const int m = blockIdx.x - LIF_BLOCKS;
        const int j = m >> 1;
        const int cbase = (m & 1) * 128;
        const int ci = threadIdx.x & 127;
        const int c = cbase + ci;
        float* sA = smem;                               // [128][6] used

        if (threadIdx.x < 128) {
            float f[12];
            {
                const float2* p = reinterpret_cast<const float2*>(fw + ((size_t)j * 256 + c) * 18);
                #pragma unroll
                for (int i = 0; i < 6; i++) { float2 v = p[i]; f[2*i] = v.x; f[2*i+1] = v.y; }
            }
            float s[5];
            #pragma unroll
            for (int t = 0; t < 5; t++) s[t] = 0.f;
            {
                float a[18];
                const float2* p = reinterpret_cast<const float2*>(w3 + c * 18);
                #pragma unroll
                for (int i = 0; i < 9; i++) { float2 v = p[i]; a[2*i] = v.x; a[2*i+1] = v.y; }
                #pragma unroll
                for (int d = 0; d < 6; d++)
                    #pragma unroll
                    for (int t = 0; t < 3; t++) s[t] = fmaf(f[d], a[d*3+t], s[t]);
            }
            {
                float a[30];
                const float2* p = reinterpret_cast<const float2*>(w5 + c * 30);
                #pragma unroll
                for (int i = 0; i < 15; i++) { float2 v = p[i]; a[2*i] = v.x; a[2*i+1] = v.y; }
                #pragma unroll
                for (int d = 0; d < 6; d++)
                    #pragma unroll
                    for (int t = 0; t < 5; t++) s[t] = fmaf(f[6+d], a[d*5+t], s[t]);
            }
            #pragma unroll
            for (int t = 0; t < 5; t++) sA[ci * 6 + t] = s[t];
            __syncthreads();
        } else {
            float f[6];
            {
                const float2* p = reinterpret_cast<const float2*>(fw + ((size_t)j * 256 + c) * 18 + 12);
                #pragma unroll
                for (int i = 0; i < 3; i++) { float2 v = p[i]; f[2*i] = v.x; f[2*i+1] = v.y; }
            }
            const float g = og[(size_t)j * 256 + c];
            float s[9];
            #pragma unroll
            for (int t = 0; t < 9; t++) s[t] = 0.f;
            {
                float a[54];
                const float2* p = reinterpret_cast<const float2*>(w9 + c * 54);
                #pragma unroll
                for (int i = 0; i < 27; i++) { float2 v = p[i]; a[2*i] = v.x; a[2*i+1] = v.y; }
                #pragma unroll
                for (int d = 0; d < 6; d++)
                    #pragma unroll
                    for (int t = 0; t < 9; t++) s[t] = fmaf(f[d], a[d*9+t], s[t]);
            }
            __syncthreads();
            #pragma unroll
            for (int t = 0; t < 5; t++) s[t] += sA[ci * 6 + t];
            #pragma unroll
            for (int t = 0; t < 9; t++) g_M[j][t][c] = g * s[t];
        }
    }
}

// ---------------------------------------------------------------------------
// recon_head: only the t<9 head is nonzero (tail zero-filled by fused kernel).
// One block per j. Stage act (16x257) + M[j] (9x257) in padded smem; threads
// 0..143 each compute one (b,t) via a 256-step smem dot product.
// ---------------------------------------------------------------------------
#define SPAD 257
__global__ void __launch_bounds__(256)
recon_head(const float* __restrict__ act, float* __restrict__ recon) {
    __shared__ float sact[16 * SPAD];
    __shared__ float sM[9 * SPAD];
    const int j = blockIdx.x;
    const int tid = threadIdx.x;

    #pragma unroll
    for (int b = 0; b < 16; b++) sact[b * SPAD + tid] = act[b * 256 + tid];
    #pragma unroll
    for (int t = 0; t < 9; t++) sM[t * SPAD + tid] = g_M[j][t][tid];
    __syncthreads();

    if (tid < 144) {
        const int b = tid / 9, t = tid % 9;
        const float* ma = sM + t * SPAD;
        const float* aa = sact + b * SPAD;
        float a0 = 0.f, a1 = 0.f, a2 = 0.f, a3 = 0.f;
        #pragma unroll
        for (int c = 0; c < 256; c += 4) {
            a0 = fmaf(ma[c + 0], aa[c + 0], a0);
            a1 = fmaf(ma[c + 1], aa[c + 1], a1);
            a2 = fmaf(ma[c + 2], aa[c + 2], a2);
            a3 = fmaf(ma[c + 3], aa[c + 3], a3);
        }
        recon[((size_t)b * 256 + j) * TT + t] = (a0 + a1) + (a2 + a3);
    }
}

// ---------------------------------------------------------------------------
extern "C" void kernel_launch(void* const* d_in, const int* in_sizes, int n_in,
                              void* d_out, int out_size) {
    const float* x  = (const float*)d_in[0];
    const float* w3 = (const float*)d_in[1];
    const float* b3 = (const float*)d_in[2];
    const float* w5 = (const float*)d_in[3];
    const float* b5 = (const float*)d_in[4];
    const float* w9 = (const float*)d_in[5];
    const float* b9 = (const float*)d_in[6];
    const float* rw = (const float*)d_in[7];
    const float* rb = (const float*)d_in[8];
    const float* ls = (const float*)d_in[9];
    const float* og = (const float*)d_in[10];
    const float* fw = (const float*)d_in[11];

    float* out      = (float*)d_out;
    float* recon    = out;                         // (B,C,T)  4194304
    float* out_x    = out + 4194304;               // (B,C,T)  4194304
    float* out_lat  = out + 8388608;               // (B,C)       4096
    float* out_act  = out + 8392704;               // (B,C)       4096

    fused_kernel<<<LIF_BLOCKS + PREP_BLOCKS + ZF_BLOCKS, 256>>>(
        x, w3, b3, w5, b5, w9, b9, rw, rb, ls, og, fw,
        out_x, out_lat, out_act, recon);
    recon_head<<<256, 256>>>(out_act, recon);
}

// round 5
// speedup vs baseline: 1.0443x; 1.0443x over previous
#include <cuda_runtime.h>
#include <cuda_bf16.h>
#include <cstdint>

#define BB 16
#define CC 256
#define TT 1024

// Precomputed table (device global: no allocation allowed)
__device__ float g_M[256][9][256];    // [j][t][c]

// ---------------------------------------------------------------------------
// Fused kernel:
//   blocks [0,512)    : LIF (8 rows each, effw computed in-warp)
//   blocks [512,1024) : M[j][t][c-half] prep (j=(bid-512)>>1, half=bid&1)
// ---------------------------------------------------------------------------
#define LIF_BLOCKS 512
#define PREP_BLOCKS 512
__global__ void __launch_bounds__(256)
fused_kernel(const float* __restrict__ x,
             const float* __restrict__ w3, const float* __restrict__ b3,
             const float* __restrict__ w5, const float* __restrict__ b5,
             const float* __restrict__ w9, const float* __restrict__ b9,
             const float* __restrict__ rw, const float* __restrict__ rb,
             const float* __restrict__ ls,
             const float* __restrict__ og, const float* __restrict__ fw,
             float* __restrict__ out_x, float* __restrict__ out_lat,
             float* __restrict__ out_act) {
    __shared__ float smem[8 * 33 * 32];                 // 33792 B, reused by roles

    if (blockIdx.x < LIF_BLOCKS) {
        // =================== LIF role ===================
        const int warp = threadIdx.x >> 5, lane = threadIdx.x & 31;
        const int row = blockIdx.x * 8 + warp;          // b*256+c
        const int c = row & 255;
        const float* xr = x + (size_t)row * TT;
        float* xo = out_x + (size_t)row * TT;
        float* sp = smem + warp * (33 * 32);

        // stage x: coalesced LDG.128, fused passthrough STG.128, conflict-free STS
        #pragma unroll
        for (int i = 0; i < 8; i++) {
            const int p = i * 128 + lane * 4;
            float4 v = *(const float4*)(xr + p);
            *(float4*)(xo + p) = v;
            const int base = 33 * (p >> 5) + (p & 31);
            sp[base + 0] = v.x; sp[base + 1] = v.y; sp[base + 2] = v.z; sp[base + 3] = v.w;
        }

        // ---- per-warp effective 9-tap kernel: lane d in [0,18) handles one dendrite ----
        float ew[9];
        #pragma unroll
        for (int i = 0; i < 9; i++) ew[i] = 0.f;
        float eb = 0.f;
        {
            const int d = lane;
            if (d < 6) {
                float r = rw[c * 18 + d];
                eb = r * b3[c * 6 + d];
                #pragma unroll
                for (int i = 0; i < 3; i++) ew[i + 3] = r * w3[(c * 6 + d) * 3 + i];
            } else if (d < 12) {
                int dd = d - 6;
                float r = rw[c * 18 + d];
                eb = r * b5[c * 6 + dd];
                #pragma unroll
                for (int i = 0; i < 5; i++) ew[i + 2] = r * w5[(c * 6 + dd) * 5 + i];
            } else if (d < 18) {
                int dd = d - 12;
                float r = rw[c * 18 + d];
                eb = r * b9[c * 6 + dd];
                #pragma unroll
                for (int i = 0; i < 9; i++) ew[i] = r * w9[(c * 6 + dd) * 9 + i];
            } else if (d == 31) {
                eb = rb[c];
            }
        }
        // butterfly reduce -> every lane gets full ew/eb
        #pragma unroll
        for (int off = 16; off; off >>= 1) {
            #pragma unroll
            for (int i = 0; i < 9; i++) ew[i] += __shfl_xor_sync(0xffffffffu, ew[i], off);
            eb += __shfl_xor_sync(0xffffffffu, eb, off);
        }
        __syncwarp();

        const float AL  = (float)0.81873075307798185567;   // exp(-1/5)
        const float OM  = (float)0.18126924692201814433;   // 1 - alpha
        const float A32 = (float)0.00166155727317393354;   // alpha^32

        const int sb = 33 * lane;
        float dloc[32];

        {   // outputs 0..7, t-offsets -4..11
            float w[16];
            #pragma unroll
            for (int q = 0; q < 4; q++)  w[q] = (lane > 0) ? sp[sb - 5 + q] : 0.f;
            #pragma unroll
            for (int q = 4; q < 16; q++) w[q] = sp[sb + q - 4];
            #pragma unroll
            for (int k = 0; k < 8; k++) {
                float d = eb;
                #pragma unroll
                for (int i = 0; i < 9; i++) d = fmaf(ew[i], w[k + i], d);
                dloc[k] = d;
            }
        }
        {   // outputs 8..15
            float w[16];
            #pragma unroll
            for (int q = 0; q < 16; q++) w[q] = sp[sb + 4 + q];
            #pragma unroll
            for (int k = 0; k < 8; k++) {
                float d = eb;
                #pragma unroll
                for (int i = 0; i < 9; i++) d = fmaf(ew[i], w[k + i], d);
                dloc[8 + k] = d;
            }
        }
        {   // outputs 16..23
            float w[16];
            #pragma unroll
            for (int q = 0; q < 16; q++) w[q] = sp[sb + 12 + q];
            #pragma unroll
            for (int k = 0; k < 8; k++) {
                float d = eb;
                #pragma unroll
                for (int i = 0; i < 9; i++) d = fmaf(ew[i], w[k + i], d);
                dloc[16 + k] = d;
            }
        }
        {   // outputs 24..31 (cross into lane+1 at offset 32)
            float w[16];
            #pragma unroll
            for (int q = 0; q < 12; q++)  w[q] = sp[sb + 20 + q];
            #pragma unroll
            for (int q = 12; q < 16; q++) w[q] = (lane < 31) ? sp[sb + 21 + q] : 0.f;
            #pragma unroll
            for (int k = 0; k < 8; k++) {
                float d = eb;
                #pragma unroll
                for (int i = 0; i < 9; i++) d = fmaf(ew[i], w[k + i], d);
                dloc[24 + k] = d;
            }
        }

        // pass 1: local segment value from V=0
        float U = 0.f, A = A32;
        #pragma unroll
        for (int ss = 0; ss < 32; ss++) U = fmaf(AL, U, OM * dloc[ss]);

        // Kogge-Stone scan over (A,U): (A1,U1)∘(A2,U2) = (A1*A2, A2*U1+U2)
        #pragma unroll
        for (int off = 1; off < 32; off <<= 1) {
            float Au = __shfl_up_sync(0xffffffffu, A, off);
            float Uu = __shfl_up_sync(0xffffffffu, U, off);
            if (lane >= off) { U = fmaf(A, Uu, U); A *= Au; }
        }
        float Vin = __shfl_up_sync(0xffffffffu, U, 1);
        if (lane == 0) Vin = 0.f;

        // pass 2: exact-order replay, first crossing
        float V = Vin;
        int lat = TT;
        const int t0 = lane * 32;
        #pragma unroll
        for (int ss = 0; ss < 32; ss++) {
            V = fmaf(AL, V, OM * dloc[ss]);
            if (lat == TT && V >= 0.01f) lat = t0 + ss;
        }
        #pragma unroll
        for (int off = 16; off; off >>= 1) lat = min(lat, __shfl_xor_sync(0xffffffffu, lat, off));

        if (lane == 0) {
            float latf = (float)lat;
            float sc = fmaxf(ls[0], 0.001f);
            out_lat[row] = latf;
            out_act[row] = expf(-latf / sc);
        }
    } else {
        // =================== M-prep role ===================
        const int m = blockIdx.x - LIF_BLOCKS;
        const int j = m >> 1;
        const int cbase = (m & 1) * 128;
        const int ci = threadIdx.x & 127;
        const int c = cbase + ci;
        float* sA = smem;                               // [128][6] used

        if (threadIdx.x < 128) {
            float f[12];
            {
                const float2* p = reinterpret_cast<const float2*>(fw + ((size_t)j * 256 + c) * 18);
                #pragma unroll
                for (int i = 0; i < 6; i++) { float2 v = p[i]; f[2*i] = v.x; f[2*i+1] = v.y; }
            }
            float s[5];
            #pragma unroll
            for (int t = 0; t < 5; t++) s[t] = 0.f;
            {
                float a[18];
                const float2* p = reinterpret_cast<const float2*>(w3 + c * 18);
                #pragma unroll
                for (int i = 0; i < 9; i++) { float2 v = p[i]; a[2*i] = v.x; a[2*i+1] = v.y; }
                #pragma unroll
                for (int d = 0; d < 6; d++)
                    #pragma unroll
                    for (int t = 0; t < 3; t++) s[t] = fmaf(f[d], a[d*3+t], s[t]);
            }
            {
                float a[30];
                const float2* p = reinterpret_cast<const float2*>(w5 + c * 30);
                #pragma unroll
                for (int i = 0; i < 15; i++) { float2 v = p[i]; a[2*i] = v.x; a[2*i+1] = v.y; }
                #pragma unroll
                for (int d = 0; d < 6; d++)
                    #pragma unroll
                    for (int t = 0; t < 5; t++) s[t] = fmaf(f[6+d], a[d*5+t], s[t]);
            }
            #pragma unroll
            for (int t = 0; t < 5; t++) sA[ci * 6 + t] = s[t];
            __syncthreads();
        } else {
            float f[6];
            {
                const float2* p = reinterpret_cast<const float2*>(fw + ((size_t)j * 256 + c) * 18 + 12);
                #pragma unroll
                for (int i = 0; i < 3; i++) { float2 v = p[i]; f[2*i] = v.x; f[2*i+1] = v.y; }
            }
            const float g = og[(size_t)j * 256 + c];
            float s[9];
            #pragma unroll
            for (int t = 0; t < 9; t++) s[t] = 0.f;
            {
                float a[54];
                const float2* p = reinterpret_cast<const float2*>(w9 + c * 54);
                #pragma unroll
                for (int i = 0; i < 27; i++) { float2 v = p[i]; a[2*i] = v.x; a[2*i+1] = v.y; }
                #pragma unroll
                for (int d = 0; d < 6; d++)
                    #pragma unroll
                    for (int t = 0; t < 9; t++) s[t] = fmaf(f[d], a[d*9+t], s[t]);
            }
            __syncthreads();
            #pragma unroll
            for (int t = 0; t < 5; t++) s[t] += sA[ci * 6 + t];
            #pragma unroll
            for (int t = 0; t < 9; t++) g_M[j][t][c] = g * s[t];
        }
    }
}

// ---------------------------------------------------------------------------
// recon: one warp per (b,j) row; M[j] in registers; warp writes its whole
// 4KB row (9-float head + zero tail). grid (256 j, 4 bq) x 128 threads.
// ---------------------------------------------------------------------------
__global__ void __launch_bounds__(128)
recon_kernel(const float* __restrict__ act, float* __restrict__ recon) {
    const int warp = threadIdx.x >> 5, lane = threadIdx.x & 31;
    const int j = blockIdx.x;
    const int b = blockIdx.y * 4 + warp;

    // load M[j][t][lane+32k] into regs (L1/L2 cached across the 4 bq blocks)
    float mreg[72];                                     // [t*8+k]
    #pragma unroll
    for (int t = 0; t < 9; t++)
        #pragma unroll
        for (int k = 0; k < 8; k++)
            mreg[t * 8 + k] = g_M[j][t][lane + 32 * k];

    float sums[9];
    #pragma unroll
    for (int t = 0; t < 9; t++) sums[t] = 0.f;
    #pragma unroll
    for (int k = 0; k < 8; k++) {
        float a = act[b * 256 + lane + 32 * k];
        #pragma unroll
        for (int t = 0; t < 9; t++) sums[t] = fmaf(a, mreg[t * 8 + k], sums[t]);
    }
    #pragma unroll
    for (int t = 0; t < 9; t++) {
        #pragma unroll
        for (int off = 16; off; off >>= 1)
            sums[t] += __shfl_xor_sync(0xffffffffu, sums[t], off);
    }

    float* r = recon + ((size_t)b * 256 + j) * TT;
    #pragma unroll
    for (int i = 0; i < 8; i++) {
        int p = i * 128 + lane * 4;
        float4 v = make_float4(0.f, 0.f, 0.f, 0.f);
        if (i == 0) {
            if (lane == 0)      v = make_float4(sums[0], sums[1], sums[2], sums[3]);
            else if (lane == 1) v = make_float4(sums[4], sums[5], sums[6], sums[7]);
            else if (lane == 2) v = make_float4(sums[8], 0.f, 0.f, 0.f);
        }
        *(float4*)(r + p) = v;
    }
}

// ---------------------------------------------------------------------------
extern "C" void kernel_launch(void* const* d_in, const int* in_sizes, int n_in,
                              void* d_out, int out_size) {
    const float* x  = (const float*)d_in[0];
    const float* w3 = (const float*)d_in[1];
    const float* b3 = (const float*)d_in[2];
    const float* w5 = (const float*)d_in[3];
    const float* b5 = (const float*)d_in[4];
    const float* w9 = (const float*)d_in[5];
    const float* b9 = (const float*)d_in[6];
    const float* rw = (const float*)d_in[7];
    const float* rb = (const float*)d_in[8];
    const float* ls = (const float*)d_in[9];
    const float* og = (const float*)d_in[10];
    const float* fw = (const float*)d_in[11];

    float* out      = (float*)d_out;
    float* recon    = out;                         // (B,C,T)  4194304
    float* out_x    = out + 4194304;               // (B,C,T)  4194304
    float* out_lat  = out + 8388608;               // (B,C)       4096
    float* out_act  = out + 8392704;               // (B,C)       4096

    fused_kernel<<<LIF_BLOCKS + PREP_BLOCKS, 256>>>(
        x, w3, b3, w5, b5, w9, b9, rw, rb, ls, og, fw,
        out_x, out_lat, out_act);
    recon_kernel<<<dim3(256, 4), 128>>>(out_act, recon);
}